// round 4
// baseline (speedup 1.0000x reference)
#include <cuda_runtime.h>
#include <cuda_bf16.h>
#include <math.h>
#include <stdint.h>

// ---------------------------------------------------------------- constants
#define N_TOK 16384
#define NE    4096
#define ED    64
#define BM    128          // tokens per CTA
#define BN    128          // codes per chunk
#define NCH   (NE/BN)      // 32
#define NBLK  (N_TOK/BM)   // 128
#define EPSW  1.7e-5f      // covers reference fp32 reorder slack (1.53e-5) + approx err

#define OUT_ZQ_OFF   1
#define OUT_IDX_OFF  (1 + (size_t)N_TOK*ED)
#define OUT_PERP_OFF (OUT_IDX_OFF + N_TOK)

// SMEM layout of vq_main
#define OFF_A    0                 // A hi 16K + A lo 16K
#define OFF_B    32768             // 2 bufs x (hi 16K + lo 16K)
#define OFF_SES  98304             // 16K fp32 ||e||^2
#define SMEM_MAIN (OFF_SES + NE*4) // 114688

// ---------------------------------------------------------------- scratch
__device__ __align__(16) __nv_bfloat16 d_zhi[N_TOK*ED];   // hi(-2z)
__device__ __align__(16) __nv_bfloat16 d_zlo[N_TOK*ED];   // lo(-2z)
__device__ __align__(16) __nv_bfloat16 d_chi[NE*ED];      // hi(e)
__device__ __align__(16) __nv_bfloat16 d_clo[NE*ED];      // lo(e)
__device__ float d_sz[N_TOK];
__device__ float d_se[NE];
__device__ int   d_counts[NE];
__device__ float d_losstok[N_TOK];
__device__ float d_bd[(size_t)N_TOK*32];   // best-8 per lane-group x4
__device__ int   d_bi[(size_t)N_TOK*32];

// ---------------------------------------------------------------- utils
static __device__ __forceinline__ uint32_t smem_u32(const void* p) {
    uint32_t a;
    asm("{ .reg .u64 t; cvta.to.shared.u64 t, %1; cvt.u32.u64 %0, t; }"
        : "=r"(a) : "l"(p));
    return a;
}
static __device__ __forceinline__ uint32_t swz(uint32_t o) { return o ^ ((o >> 3) & 0x70); }

static __device__ __forceinline__ void ldsm4(uint32_t& r0, uint32_t& r1,
                                             uint32_t& r2, uint32_t& r3, uint32_t a) {
    asm volatile("ldmatrix.sync.aligned.m8n8.x4.shared.b16 {%0,%1,%2,%3}, [%4];"
                 : "=r"(r0), "=r"(r1), "=r"(r2), "=r"(r3) : "r"(a));
}
static __device__ __forceinline__ void mma_bf16(float c[4], const uint32_t a[4],
                                                uint32_t b0, uint32_t b1) {
    asm volatile("mma.sync.aligned.m16n8k16.row.col.f32.bf16.bf16.f32 "
                 "{%0,%1,%2,%3}, {%4,%5,%6,%7}, {%8,%9}, {%0,%1,%2,%3};"
                 : "+f"(c[0]), "+f"(c[1]), "+f"(c[2]), "+f"(c[3])
                 : "r"(a[0]), "r"(a[1]), "r"(a[2]), "r"(a[3]), "r"(b0), "r"(b1));
}
#define CP_ASYNC16(s, g) \
    asm volatile("cp.async.cg.shared.global [%0], [%1], 16;" :: "r"(s), "l"(g))
#define CP_COMMIT() asm volatile("cp.async.commit_group;" ::: "memory")
#define CP_WAIT(n)  asm volatile("cp.async.wait_group %0;" :: "n"(n) : "memory")

// best-8 sorted insert; increasing-k processing order => ties keep first index
#define INS(bv, bix, dv, kk) do { \
    if ((dv) < bv[7]) { \
        bv[7] = (dv); bix[7] = (kk); \
        _Pragma("unroll") \
        for (int _j = 7; _j > 0; _j--) { \
            if (bv[_j] < bv[_j-1]) { \
                float _tv = bv[_j]; bv[_j] = bv[_j-1]; bv[_j-1] = _tv; \
                int _ti = bix[_j]; bix[_j] = bix[_j-1]; bix[_j-1] = _ti; } \
        } \
    } \
} while (0)

// ---------------------------------------------------------------- prep
// hi/lo bf16 split of (-2z) and (e); row squared norms; zero counts.
__global__ void __launch_bounds__(256) vq_prep(const float* __restrict__ z,
                                               const float* __restrict__ cb) {
    int b = blockIdx.x, tid = threadIdx.x;
    if (b == 2560) {
        for (int i = tid; i < NE; i += 256) d_counts[i] = 0;
        return;
    }
    int w = tid >> 5, lane = tid & 31;
    int row = b * 8 + w;
    const float* src; __nv_bfloat16 *hi, *lo; float* nr; int r; float sc;
    if (row < N_TOK) { src = z;  hi = d_zhi; lo = d_zlo; nr = d_sz; r = row;         sc = -2.0f; }
    else             { src = cb; hi = d_chi; lo = d_clo; nr = d_se; r = row - N_TOK; sc =  1.0f; }

    float2 v = *(const float2*)&src[(size_t)r * ED + lane * 2];
    float m0 = sc * v.x, m1 = sc * v.y;
    __nv_bfloat16 h0 = __float2bfloat16(m0), h1 = __float2bfloat16(m1);
    float l0 = m0 - __bfloat162float(h0), l1 = m1 - __bfloat162float(h1);
    __nv_bfloat162 hh; hh.x = h0; hh.y = h1;
    __nv_bfloat162 ll; ll.x = __float2bfloat16(l0); ll.y = __float2bfloat16(l1);
    ((__nv_bfloat162*)hi)[(size_t)r * 32 + lane] = hh;
    ((__nv_bfloat162*)lo)[(size_t)r * 32 + lane] = ll;

    float s = __fmaf_rn(v.x, v.x, v.y * v.y);
    #pragma unroll
    for (int o = 16; o; o >>= 1) s += __shfl_xor_sync(0xffffffffu, s, o);
    if (lane == 0) nr[r] = s;
}

// ---------------------------------------------------------------- main
static __device__ __forceinline__ void load_b(uint32_t sb, int ch, int buf) {
    int tid = threadIdx.x;
    size_t k0 = (size_t)ch * BN;
    uint32_t bhi = sb + OFF_B + (uint32_t)buf * 32768u;
    uint32_t blo = bhi + 16384u;
    #pragma unroll
    for (int p = 0; p < 4; p++) {
        int l = tid + p * 256;
        int row = l >> 3, seg = l & 7;
        uint32_t sw = swz((uint32_t)(row * 128 + seg * 16));
        size_t g = ((k0 + row) * ED + seg * 8) * 2;
        CP_ASYNC16(bhi + sw, (const char*)d_chi + g);
        CP_ASYNC16(blo + sw, (const char*)d_clo + g);
    }
}

__global__ void __launch_bounds__(256, 1) vq_main() {
    extern __shared__ char smem[];
    uint32_t sb = smem_u32(smem);
    const int tid = threadIdx.x;
    const int w = tid >> 5, lid = tid & 31;
    const int m0 = blockIdx.x * BM;

    // stage A (hi/lo of -2z) with SW128
    #pragma unroll
    for (int p = 0; p < 4; p++) {
        int l = tid + p * 256;
        int row = l >> 3, seg = l & 7;
        uint32_t sw = swz((uint32_t)(row * 128 + seg * 16));
        size_t g = (((size_t)(m0 + row)) * ED + seg * 8) * 2;
        *(uint4*)(smem + OFF_A + sw)         = *(const uint4*)((const char*)d_zhi + g);
        *(uint4*)(smem + OFF_A + 16384 + sw) = *(const uint4*)((const char*)d_zlo + g);
    }
    float* ses = (float*)(smem + OFF_SES);
    for (int i = tid; i < NE; i += 256) ses[i] = d_se[i];
    __syncthreads();

    // A fragments (once; reused across all chunks)
    uint32_t ahi[4][4], alo[4][4];
    {
        int arow = w * 16 + (lid & 7) + ((lid >> 3) & 1) * 8;
        #pragma unroll
        for (int ks = 0; ks < 4; ks++) {
            uint32_t off = swz((uint32_t)(arow * 128 + ks * 32 + (lid >> 4) * 16));
            ldsm4(ahi[ks][0], ahi[ks][1], ahi[ks][2], ahi[ks][3], sb + OFF_A + off);
            ldsm4(alo[ks][0], alo[ks][1], alo[ks][2], alo[ks][3], sb + OFF_A + 16384u + off);
        }
    }

    float r0v[8], r1v[8]; int r0i[8], r1i[8];
    #pragma unroll
    for (int j = 0; j < 8; j++) {
        r0v[j] = 3.4e38f; r1v[j] = 3.4e38f; r0i[j] = 0x7fffffff; r1i[j] = 0x7fffffff;
    }

    load_b(sb, 0, 0);
    CP_COMMIT();

    const int brow_l = (lid & 7) + ((lid >> 3) & 1) * 8;
    const int boff_l = (lid >> 4) * 16;

    for (int ch = 0; ch < NCH; ch++) {
        if (ch + 1 < NCH) { load_b(sb, ch + 1, (ch + 1) & 1); CP_COMMIT(); }
        if (ch + 1 < NCH) CP_WAIT(1); else CP_WAIT(0);
        __syncthreads();

        uint32_t bhi_base = sb + OFF_B + (uint32_t)((ch & 1) * 32768);
        uint32_t blo_base = bhi_base + 16384u;

        #pragma unroll
        for (int nt2 = 0; nt2 < 8; nt2++) {
            float aE[4] = {0.f, 0.f, 0.f, 0.f};
            float aO[4] = {0.f, 0.f, 0.f, 0.f};
            #pragma unroll
            for (int ks = 0; ks < 4; ks++) {
                uint32_t sa = swz((uint32_t)((nt2 * 16 + brow_l) * 128 + ks * 32 + boff_l));
                uint32_t h0, h1, h2, h3, q0, q1, q2, q3;
                ldsm4(h0, h1, h2, h3, bhi_base + sa);
                ldsm4(q0, q1, q2, q3, blo_base + sa);
                mma_bf16(aE, ahi[ks], h0, h2);   // hi . hi
                mma_bf16(aO, ahi[ks], h1, h3);
                mma_bf16(aE, ahi[ks], q0, q2);   // hi . lo
                mma_bf16(aO, ahi[ks], q1, q3);
                mma_bf16(aE, alo[ks], h0, h2);   // lo . hi
                mma_bf16(aO, alo[ks], h1, h3);
            }
            // epilogue: dv = se + (-2 dot); sz is row-constant -> dropped
            int cE = nt2 * 16 + 2 * (lid & 3);
            float2 sE = *(const float2*)&ses[ch * BN + cE];
            float2 sO = *(const float2*)&ses[ch * BN + cE + 8];
            int kg = ch * BN + cE;
            float dv;
            dv = __fadd_rn(aE[0], sE.x); INS(r0v, r0i, dv, kg);
            dv = __fadd_rn(aE[1], sE.y); INS(r0v, r0i, dv, kg + 1);
            dv = __fadd_rn(aO[0], sO.x); INS(r0v, r0i, dv, kg + 8);
            dv = __fadd_rn(aO[1], sO.y); INS(r0v, r0i, dv, kg + 9);
            dv = __fadd_rn(aE[2], sE.x); INS(r1v, r1i, dv, kg);
            dv = __fadd_rn(aE[3], sE.y); INS(r1v, r1i, dv, kg + 1);
            dv = __fadd_rn(aO[2], sO.x); INS(r1v, r1i, dv, kg + 8);
            dv = __fadd_rn(aO[3], sO.y); INS(r1v, r1i, dv, kg + 9);
        }
        __syncthreads();
    }

    int t0 = m0 + w * 16 + (lid >> 2);
    size_t b0 = (size_t)t0 * 32 + (size_t)(lid & 3) * 8;
    size_t b1 = (size_t)(t0 + 8) * 32 + (size_t)(lid & 3) * 8;
    #pragma unroll
    for (int j = 0; j < 8; j++) {
        d_bd[b0 + j] = r0v[j]; d_bi[b0 + j] = r0i[j];
        d_bd[b1 + j] = r1v[j]; d_bi[b1 + j] = r1i[j];
    }
}

// ---------------------------------------------------------------- resolve
// Warp per token: exact (reference-chain) rescore of ambiguous candidates.
static __device__ __forceinline__ float exact_d(const float* __restrict__ z,
                                                const float* __restrict__ cb,
                                                int t, int ic) {
    const float* zr = z + (size_t)t * ED;
    const float* cr = cb + (size_t)ic * ED;
    float dot = 0.f;
    #pragma unroll
    for (int d = 0; d < ED; d++) dot = __fmaf_rn(zr[d], cr[d], dot);
    return __fmaf_rn(-2.0f, dot, __fadd_rn(d_sz[t], d_se[ic]));
}

__global__ void __launch_bounds__(256) vq_resolve(const float* __restrict__ z,
                                                  const float* __restrict__ cb,
                                                  float* __restrict__ out) {
    int gw = (blockIdx.x * 256 + threadIdx.x) >> 5;   // token
    int l = threadIdx.x & 31;
    int t = gw;

    float v = d_bd[(size_t)t * 32 + l];
    int   ix = d_bi[(size_t)t * 32 + l];

    // global approx min with index tie-break
    float gv = v; int gi = ix;
    #pragma unroll
    for (int o = 16; o; o >>= 1) {
        float ov = __shfl_xor_sync(0xffffffffu, gv, o);
        int   oi = __shfl_xor_sync(0xffffffffu, gi, o);
        if (ov < gv || (ov == gv && oi < gi)) { gv = ov; gi = oi; }
    }
    float thr = gv + EPSW;

    // flag: some lane-group's 8th-best inside window -> full exact scan
    unsigned flagm = __ballot_sync(0xffffffffu, ((l & 7) == 7) && (v <= thr));
    unsigned candm = __ballot_sync(0xffffffffu, v <= thr);

    int winner;
    if (flagm) {
        float bv = 3.4e38f; int bi_ = 0x7fffffff;
        for (int c = l; c < NE; c += 32) {
            float dv = exact_d(z, cb, t, c);
            if (dv < bv) { bv = dv; bi_ = c; }
        }
        #pragma unroll
        for (int o = 16; o; o >>= 1) {
            float ov = __shfl_xor_sync(0xffffffffu, bv, o);
            int   oi = __shfl_xor_sync(0xffffffffu, bi_, o);
            if (ov < bv || (ov == bv && oi < bi_)) { bv = ov; bi_ = oi; }
        }
        winner = bi_;
    } else if (__popc(candm) > 1) {
        float bv = 3.4e38f; int bi_ = 0x7fffffff;
        if (v <= thr) { bv = exact_d(z, cb, t, ix); bi_ = ix; }
        #pragma unroll
        for (int o = 16; o; o >>= 1) {
            float ov = __shfl_xor_sync(0xffffffffu, bv, o);
            int   oi = __shfl_xor_sync(0xffffffffu, bi_, o);
            if (ov < bv || (ov == bv && oi < bi_)) { bv = ov; bi_ = oi; }
        }
        winner = bi_;
    } else {
        winner = gi;
    }

    if (l == 0) {
        out[OUT_IDX_OFF + t] = (float)winner;
        atomicAdd(&d_counts[winner], 1);
    }

    // z_q_st + per-token loss partial (deterministic fixed-order shfl tree)
    float lacc = 0.f;
    #pragma unroll
    for (int p = 0; p < 2; p++) {
        int d = l + p * 32;
        float zq = cb[(size_t)winner * ED + d];
        float zv = z[(size_t)t * ED + d];
        float tt = __fsub_rn(zq, zv);
        out[OUT_ZQ_OFF + (size_t)t * ED + d] = __fadd_rn(zv, tt);
        lacc = __fmaf_rn(tt, tt, lacc);
    }
    #pragma unroll
    for (int o = 16; o; o >>= 1) lacc += __shfl_xor_sync(0xffffffffu, lacc, o);
    if (l == 0) d_losstok[t] = lacc;
}

// ---------------------------------------------------------------- finalize
__global__ void __launch_bounds__(256) vq_finalize(float* __restrict__ out) {
    __shared__ double sh[256];
    int tid = threadIdx.x;
    double s = 0.0;
    for (int i = tid; i < N_TOK; i += 256) s += (double)d_losstok[i];
    sh[tid] = s;
    __syncthreads();
    #pragma unroll
    for (int st = 128; st > 0; st >>= 1) {
        if (tid < st) sh[tid] += sh[tid + st];
        __syncthreads();
    }
    if (tid == 0)
        out[0] = (float)(1.25 * sh[0] / (double)((size_t)N_TOK * ED));
    __syncthreads();

    double h = 0.0;
    for (int i = tid; i < NE; i += 256) {
        float em = (float)d_counts[i] / (float)N_TOK;
        h += (double)(em * logf(em + 1e-10f));
    }
    sh[tid] = h;
    __syncthreads();
    #pragma unroll
    for (int st = 128; st > 0; st >>= 1) {
        if (tid < st) sh[tid] += sh[tid + st];
        __syncthreads();
    }
    if (tid == 0)
        out[OUT_PERP_OFF] = expf(-(float)sh[0]);
}

// ---------------------------------------------------------------- launch
extern "C" void kernel_launch(void* const* d_in, const int* in_sizes, int n_in,
                              void* d_out, int out_size) {
    const float* z  = (const float*)d_in[0];
    const float* cb = (const float*)d_in[1];
    float* out = (float*)d_out;

    cudaFuncSetAttribute(vq_main, cudaFuncAttributeMaxDynamicSharedMemorySize, SMEM_MAIN);

    vq_prep<<<2561, 256>>>(z, cb);
    vq_main<<<NBLK, 256, SMEM_MAIN>>>();
    vq_resolve<<<N_TOK / 8, 256>>>(z, cb, out);
    vq_finalize<<<1, 256>>>(out);
}

// round 5
// speedup vs baseline: 1.0716x; 1.0716x over previous
#include <cuda_runtime.h>
#include <cuda_fp16.h>
#include <math.h>
#include <stdint.h>

// ---------------------------------------------------------------- constants
#define N_TOK 16384
#define NE    4096
#define ED    64
#define BM    128          // tokens per CTA
#define BN    128          // codes per chunk
#define NCH   (NE/BN)      // 32
#define NBLK  (N_TOK/BM)   // 128
#define EPSW  4.0e-5f      // ref fp32 reorder slack + dropped z*e_lo term

#define OUT_ZQ_OFF   1
#define OUT_IDX_OFF  (1 + (size_t)N_TOK*ED)
#define OUT_PERP_OFF (OUT_IDX_OFF + N_TOK)

// SMEM layout of vq_main
#define OFF_A    0                 // zh 16K + zl 16K
#define OFF_B    32768             // 2 bufs x 16K (eh only)
#define OFF_SES  65536             // 16K fp32 ||e||^2
#define SMEM_MAIN (OFF_SES + NE*4) // 81920

// ---------------------------------------------------------------- scratch
__device__ __align__(16) __half d_zh[N_TOK*ED];   // hi(-2z)
__device__ __align__(16) __half d_zl[N_TOK*ED];   // lo(-2z)
__device__ __align__(16) __half d_eh[NE*ED];      // hi(e)
__device__ float d_sz[N_TOK];
__device__ float d_se[NE];
__device__ int   d_counts[NE];
__device__ float d_losstok[N_TOK];
__device__ float d_bd[(size_t)N_TOK*32];
__device__ int   d_bi[(size_t)N_TOK*32];

// ---------------------------------------------------------------- utils
static __device__ __forceinline__ uint32_t smem_u32(const void* p) {
    uint32_t a;
    asm("{ .reg .u64 t; cvta.to.shared.u64 t, %1; cvt.u32.u64 %0, t; }"
        : "=r"(a) : "l"(p));
    return a;
}
static __device__ __forceinline__ uint32_t swz(uint32_t o) { return o ^ ((o >> 3) & 0x70); }

static __device__ __forceinline__ void ldsm4(uint32_t& r0, uint32_t& r1,
                                             uint32_t& r2, uint32_t& r3, uint32_t a) {
    asm volatile("ldmatrix.sync.aligned.m8n8.x4.shared.b16 {%0,%1,%2,%3}, [%4];"
                 : "=r"(r0), "=r"(r1), "=r"(r2), "=r"(r3) : "r"(a));
}
static __device__ __forceinline__ void mma_f16(float c[4], const uint32_t a[4],
                                               uint32_t b0, uint32_t b1) {
    asm volatile("mma.sync.aligned.m16n8k16.row.col.f32.f16.f16.f32 "
                 "{%0,%1,%2,%3}, {%4,%5,%6,%7}, {%8,%9}, {%0,%1,%2,%3};"
                 : "+f"(c[0]), "+f"(c[1]), "+f"(c[2]), "+f"(c[3])
                 : "r"(a[0]), "r"(a[1]), "r"(a[2]), "r"(a[3]), "r"(b0), "r"(b1));
}
#define CP_ASYNC16(s, g) \
    asm volatile("cp.async.cg.shared.global [%0], [%1], 16;" :: "r"(s), "l"(g))
#define CP_COMMIT() asm volatile("cp.async.commit_group;" ::: "memory")
#define CP_WAIT(n)  asm volatile("cp.async.wait_group %0;" :: "n"(n) : "memory")

// best-8 sorted insert; increasing-k order => ties keep first index
#define INS(bv, bix, dv, kk) do { \
    if ((dv) < bv[7]) { \
        bv[7] = (dv); bix[7] = (kk); \
        _Pragma("unroll") \
        for (int _j = 7; _j > 0; _j--) { \
            if (bv[_j] < bv[_j-1]) { \
                float _tv = bv[_j]; bv[_j] = bv[_j-1]; bv[_j-1] = _tv; \
                int _ti = bix[_j]; bix[_j] = bix[_j-1]; bix[_j-1] = _ti; } \
        } \
    } \
} while (0)

// ---------------------------------------------------------------- L1: prep
// fp16 hi/lo split of (-2z); fp16 hi of (e); row squared norms.
__global__ void __launch_bounds__(256) vq_prep(const float* __restrict__ z,
                                               const float* __restrict__ cb) {
    int b = blockIdx.x, tid = threadIdx.x;
    int w = tid >> 5, lane = tid & 31;
    int row = b * 8 + w;
    bool isz = row < N_TOK;
    const float* src = isz ? z : cb;
    int r = isz ? row : row - N_TOK;

    float2 v = *(const float2*)&src[(size_t)r * ED + lane * 2];
    float sc = isz ? -2.0f : 1.0f;
    float m0 = sc * v.x, m1 = sc * v.y;
    __half h0 = __float2half_rn(m0), h1 = __float2half_rn(m1);
    __half2 hh; hh.x = h0; hh.y = h1;
    if (isz) {
        float l0 = m0 - __half2float(h0), l1 = m1 - __half2float(h1);
        __half2 ll; ll.x = __float2half_rn(l0); ll.y = __float2half_rn(l1);
        ((__half2*)d_zh)[(size_t)r * 32 + lane] = hh;
        ((__half2*)d_zl)[(size_t)r * 32 + lane] = ll;
    } else {
        ((__half2*)d_eh)[(size_t)r * 32 + lane] = hh;
    }

    float s = __fmaf_rn(v.x, v.x, v.y * v.y);
    #pragma unroll
    for (int o = 16; o; o >>= 1) s += __shfl_xor_sync(0xffffffffu, s, o);
    if (lane == 0) (isz ? d_sz : d_se)[r] = s;
}

// ---------------------------------------------------------------- L2/L3
__global__ void __launch_bounds__(256) vq_zero() {
    int i = blockIdx.x * 256 + threadIdx.x;
    if (i < NE) d_counts[i] = 0;
}
__global__ void __launch_bounds__(256) vq_aux() {
    int i = blockIdx.x * 256 + threadIdx.x;
    if (i < N_TOK) d_losstok[i] = 0.f;
}

// ---------------------------------------------------------------- L4: main
static __device__ __forceinline__ void load_b(uint32_t sb, int ch, int buf) {
    int tid = threadIdx.x;
    size_t k0 = (size_t)ch * BN;
    uint32_t bh = sb + OFF_B + (uint32_t)buf * 16384u;
    #pragma unroll
    for (int p = 0; p < 4; p++) {
        int l = tid + p * 256;
        int row = l >> 3, seg = l & 7;
        uint32_t sw = swz((uint32_t)(row * 128 + seg * 16));
        size_t g = ((k0 + row) * ED + seg * 8) * 2;
        CP_ASYNC16(bh + sw, (const char*)d_eh + g);
    }
}

__global__ void __launch_bounds__(256, 1) vq_main() {
    extern __shared__ char smem[];
    uint32_t sb = smem_u32(smem);
    const int tid = threadIdx.x;
    const int w = tid >> 5, lid = tid & 31;
    const int m0 = blockIdx.x * BM;

    // stage A (zh/zl of -2z) with SW128
    #pragma unroll
    for (int p = 0; p < 4; p++) {
        int l = tid + p * 256;
        int row = l >> 3, seg = l & 7;
        uint32_t sw = swz((uint32_t)(row * 128 + seg * 16));
        size_t g = (((size_t)(m0 + row)) * ED + seg * 8) * 2;
        *(uint4*)(smem + OFF_A + sw)         = *(const uint4*)((const char*)d_zh + g);
        *(uint4*)(smem + OFF_A + 16384 + sw) = *(const uint4*)((const char*)d_zl + g);
    }
    float* ses = (float*)(smem + OFF_SES);
    for (int i = tid; i < NE; i += 256) ses[i] = d_se[i];
    __syncthreads();

    // A fragments once
    uint32_t ah[4][4], al[4][4];
    {
        int arow = w * 16 + (lid & 7) + ((lid >> 3) & 1) * 8;
        #pragma unroll
        for (int ks = 0; ks < 4; ks++) {
            uint32_t off = swz((uint32_t)(arow * 128 + ks * 32 + (lid >> 4) * 16));
            ldsm4(ah[ks][0], ah[ks][1], ah[ks][2], ah[ks][3], sb + OFF_A + off);
            ldsm4(al[ks][0], al[ks][1], al[ks][2], al[ks][3], sb + OFF_A + 16384u + off);
        }
    }

    float r0v[8], r1v[8]; int r0i[8], r1i[8];
    #pragma unroll
    for (int j = 0; j < 8; j++) {
        r0v[j] = 3.4e38f; r1v[j] = 3.4e38f; r0i[j] = 0x7fffffff; r1i[j] = 0x7fffffff;
    }

    load_b(sb, 0, 0);
    CP_COMMIT();

    const int brow_l = (lid & 7) + ((lid >> 3) & 1) * 8;
    const int boff_l = (lid >> 4) * 16;

    for (int ch = 0; ch < NCH; ch++) {
        if (ch + 1 < NCH) { load_b(sb, ch + 1, (ch + 1) & 1); CP_COMMIT(); }
        if (ch + 1 < NCH) CP_WAIT(1); else CP_WAIT(0);
        __syncthreads();

        uint32_t bbase = sb + OFF_B + (uint32_t)((ch & 1) * 16384);

        #pragma unroll
        for (int nt2 = 0; nt2 < 8; nt2++) {
            float aE[4] = {0.f, 0.f, 0.f, 0.f};
            float aO[4] = {0.f, 0.f, 0.f, 0.f};
            #pragma unroll
            for (int ks = 0; ks < 4; ks++) {
                uint32_t sa = swz((uint32_t)((nt2 * 16 + brow_l) * 128 + ks * 32 + boff_l));
                uint32_t h0, h1, h2, h3;
                ldsm4(h0, h1, h2, h3, bbase + sa);
                mma_f16(aE, ah[ks], h0, h2);   // zh . eh
                mma_f16(aO, ah[ks], h1, h3);
                mma_f16(aE, al[ks], h0, h2);   // zl . eh
                mma_f16(aO, al[ks], h1, h3);
            }
            int cE = nt2 * 16 + 2 * (lid & 3);
            float2 sE = *(const float2*)&ses[ch * BN + cE];
            float2 sO = *(const float2*)&ses[ch * BN + cE + 8];
            int kg = ch * BN + cE;
            float dv;
            dv = __fadd_rn(aE[0], sE.x); INS(r0v, r0i, dv, kg);
            dv = __fadd_rn(aE[1], sE.y); INS(r0v, r0i, dv, kg + 1);
            dv = __fadd_rn(aO[0], sO.x); INS(r0v, r0i, dv, kg + 8);
            dv = __fadd_rn(aO[1], sO.y); INS(r0v, r0i, dv, kg + 9);
            dv = __fadd_rn(aE[2], sE.x); INS(r1v, r1i, dv, kg);
            dv = __fadd_rn(aE[3], sE.y); INS(r1v, r1i, dv, kg + 1);
            dv = __fadd_rn(aO[2], sO.x); INS(r1v, r1i, dv, kg + 8);
            dv = __fadd_rn(aO[3], sO.y); INS(r1v, r1i, dv, kg + 9);
        }
        __syncthreads();
    }

    int t0 = m0 + w * 16 + (lid >> 2);
    size_t b0 = (size_t)t0 * 32 + (size_t)(lid & 3) * 8;
    size_t b1 = (size_t)(t0 + 8) * 32 + (size_t)(lid & 3) * 8;
    #pragma unroll
    for (int j = 0; j < 8; j++) {
        d_bd[b0 + j] = r0v[j]; d_bi[b0 + j] = r0i[j];
        d_bd[b1 + j] = r1v[j]; d_bi[b1 + j] = r1i[j];
    }
}

// ---------------------------------------------------------------- L5: resolve
static __device__ __forceinline__ float exact_d(const float* __restrict__ z,
                                                const float* __restrict__ cb,
                                                int t, int ic) {
    const float* zr = z + (size_t)t * ED;
    const float* cr = cb + (size_t)ic * ED;
    float dot = 0.f;
    #pragma unroll
    for (int d = 0; d < ED; d++) dot = __fmaf_rn(zr[d], cr[d], dot);
    return __fmaf_rn(-2.0f, dot, __fadd_rn(d_sz[t], d_se[ic]));
}

__global__ void __launch_bounds__(256) vq_resolve(const float* __restrict__ z,
                                                  const float* __restrict__ cb,
                                                  float* __restrict__ out) {
    int t = (blockIdx.x * 256 + threadIdx.x) >> 5;
    int l = threadIdx.x & 31;

    float v = d_bd[(size_t)t * 32 + l];
    int   ix = d_bi[(size_t)t * 32 + l];

    float gv = v; int gi = ix;
    #pragma unroll
    for (int o = 16; o; o >>= 1) {
        float ov = __shfl_xor_sync(0xffffffffu, gv, o);
        int   oi = __shfl_xor_sync(0xffffffffu, gi, o);
        if (ov < gv || (ov == gv && oi < gi)) { gv = ov; gi = oi; }
    }
    float thr = gv + EPSW;

    unsigned flagm = __ballot_sync(0xffffffffu, ((l & 7) == 7) && (v <= thr));
    unsigned candm = __ballot_sync(0xffffffffu, v <= thr);

    int winner;
    if (flagm) {                       // containment at risk: full exact scan
        float bv = 3.4e38f; int bi_ = 0x7fffffff;
        for (int c = l; c < NE; c += 32) {
            float dv = exact_d(z, cb, t, c);
            if (dv < bv) { bv = dv; bi_ = c; }
        }
        #pragma unroll
        for (int o = 16; o; o >>= 1) {
            float ov = __shfl_xor_sync(0xffffffffu, bv, o);
            int   oi = __shfl_xor_sync(0xffffffffu, bi_, o);
            if (ov < bv || (ov == bv && oi < bi_)) { bv = ov; bi_ = oi; }
        }
        winner = bi_;
    } else if (__popc(candm) > 1) {    // exact rescore of in-window candidates
        float bv = 3.4e38f; int bi_ = 0x7fffffff;
        if (v <= thr) { bv = exact_d(z, cb, t, ix); bi_ = ix; }
        #pragma unroll
        for (int o = 16; o; o >>= 1) {
            float ov = __shfl_xor_sync(0xffffffffu, bv, o);
            int   oi = __shfl_xor_sync(0xffffffffu, bi_, o);
            if (ov < bv || (ov == bv && oi < bi_)) { bv = ov; bi_ = oi; }
        }
        winner = bi_;
    } else {
        winner = gi;
    }

    if (l == 0) {
        out[OUT_IDX_OFF + t] = (float)winner;
        atomicAdd(&d_counts[winner], 1);
    }

    float lacc = 0.f;
    #pragma unroll
    for (int p = 0; p < 2; p++) {
        int d = l + p * 32;
        float zq = cb[(size_t)winner * ED + d];
        float zv = z[(size_t)t * ED + d];
        float tt = __fsub_rn(zq, zv);
        out[OUT_ZQ_OFF + (size_t)t * ED + d] = __fadd_rn(zv, tt);
        lacc = __fmaf_rn(tt, tt, lacc);
    }
    #pragma unroll
    for (int o = 16; o; o >>= 1) lacc += __shfl_xor_sync(0xffffffffu, lacc, o);
    if (l == 0) d_losstok[t] = lacc;
}

// ---------------------------------------------------------------- L6: finalize
__global__ void __launch_bounds__(1024) vq_finalize(float* __restrict__ out) {
    __shared__ double sh[1024];
    int tid = threadIdx.x;
    double s = 0.0;
    for (int i = tid; i < N_TOK; i += 1024) s += (double)d_losstok[i];
    sh[tid] = s;
    __syncthreads();
    #pragma unroll
    for (int st = 512; st > 0; st >>= 1) {
        if (tid < st) sh[tid] += sh[tid + st];
        __syncthreads();
    }
    if (tid == 0)
        out[0] = (float)(1.25 * sh[0] / (double)((size_t)N_TOK * ED));
    __syncthreads();

    double h = 0.0;
    for (int i = tid; i < NE; i += 1024) {
        float em = (float)d_counts[i] / (float)N_TOK;
        h += (double)(em * logf(em + 1e-10f));
    }
    sh[tid] = h;
    __syncthreads();
    #pragma unroll
    for (int st = 512; st > 0; st >>= 1) {
        if (tid < st) sh[tid] += sh[tid + st];
        __syncthreads();
    }
    if (tid == 0)
        out[OUT_PERP_OFF] = expf(-(float)sh[0]);
}

// ---------------------------------------------------------------- launch
extern "C" void kernel_launch(void* const* d_in, const int* in_sizes, int n_in,
                              void* d_out, int out_size) {
    const float* z  = (const float*)d_in[0];
    const float* cb = (const float*)d_in[1];
    float* out = (float*)d_out;

    cudaFuncSetAttribute(vq_main, cudaFuncAttributeMaxDynamicSharedMemorySize, SMEM_MAIN);

    vq_prep<<<2560, 256>>>(z, cb);         // L1
    vq_zero<<<16, 256>>>();                // L2
    vq_aux<<<64, 256>>>();                 // L3
    vq_main<<<NBLK, 256, SMEM_MAIN>>>();   // L4  <- ncu slot #6
    vq_resolve<<<N_TOK / 8, 256>>>(z, cb, out);
    vq_finalize<<<1, 1024>>>(out);
}